// round 11
// baseline (speedup 1.0000x reference)
#include <cuda_runtime.h>
#include <cuda_fp16.h>
#include <cstdint>
#include <cstddef>

// Flash attention, all-fp16 operand path, register-resident P, cp.async fp16 tiles.
//   Prepass: K,V f32 (N,S,H,E) -> fp16 __device__ scratch (N,H,S,E), done once
//            per launch so the hot loop never converts.
//   Main:    QK^T fp16 2-term split (m16n8k16); PV fp16 m16n8k16 f32-accum;
//            K/V tiles via cp.async (16B) double-buffered; ldmatrix fragments;
//            P stays in registers (C-frag == A-frag identity for fp16 k16).

#define N_DIM 2
#define L_DIM 2048
#define S_DIM 2048
#define H_DIM 16
#define BR 128
#define BC 32
#define NTILES (S_DIM / BC)
#define TEMP 0.125f

// smem byte layout
#define KROWB 144              // 64 fp16 = 128 B + 16 pad (ldmatrix conflict-free)
#define VROWB 144
#define KBUFB 4608             // 32 * 144
#define VBUFB 4608
#define OFF_KB 0               // 2 buffers -> 9216
#define OFF_VB 9216            // 2 buffers -> 9216 (end 18432)
#define QSTRIDE 68             // prologue scratch stride (floats)
#define SMEM_BYTES 34816       // Q scratch overlay dominates

// fp16 scratch, (N,H,S,E) layout: row (n,h,s) is 64 halves = 128 B contiguous
__device__ __align__(16) uint16_t g_KH[(size_t)N_DIM * H_DIM * S_DIM * 64];
__device__ __align__(16) uint16_t g_VH[(size_t)N_DIM * H_DIM * S_DIM * 64];

__device__ __forceinline__ uint32_t pack_f16(float lo, float hi) {
    uint32_t r; asm("cvt.rn.f16x2.f32 %0, %1, %2;" : "=r"(r) : "f"(hi), "f"(lo)); return r;
}
__device__ __forceinline__ float2 unpack_f16(uint32_t u) {
    __half2 h = *reinterpret_cast<__half2*>(&u);
    return __half22float2(h);
}

__device__ __forceinline__ void mma_f16(float* d, const uint32_t* a, uint32_t b0, uint32_t b1) {
    asm volatile(
        "mma.sync.aligned.m16n8k16.row.col.f32.f16.f16.f32 "
        "{%0,%1,%2,%3}, {%4,%5,%6,%7}, {%8,%9}, {%0,%1,%2,%3};"
        : "+f"(d[0]), "+f"(d[1]), "+f"(d[2]), "+f"(d[3])
        : "r"(a[0]), "r"(a[1]), "r"(a[2]), "r"(a[3]), "r"(b0), "r"(b1));
}

#define LDSM_X4(r0, r1, r2, r3, a) \
    asm volatile("ldmatrix.sync.aligned.m8n8.x4.shared.b16 {%0,%1,%2,%3}, [%4];" \
        : "=r"(r0), "=r"(r1), "=r"(r2), "=r"(r3) : "r"(a))
#define LDSM_X4_T(r0, r1, r2, r3, a) \
    asm volatile("ldmatrix.sync.aligned.m8n8.x4.trans.shared.b16 {%0,%1,%2,%3}, [%4];" \
        : "=r"(r0), "=r"(r1), "=r"(r2), "=r"(r3) : "r"(a))

#define CP_ASYNC16(dst, src) \
    asm volatile("cp.async.cg.shared.global [%0], [%1], 16;" :: "r"(dst), "l"(src))
#define CP_COMMIT() asm volatile("cp.async.commit_group;" ::: "memory")
#define CP_WAIT0()  asm volatile("cp.async.wait_group 0;" ::: "memory")

// ---- Prepass: f32 (N,S,H,E) -> fp16 (N,H,S,E) for K and V ----
#define GROUPS_PER_T ((N_DIM * S_DIM * H_DIM * 64) / 4)   // 1048576 float4-groups

__global__ __launch_bounds__(256) void cvt_kernel(
    const float* __restrict__ K, const float* __restrict__ V)
{
    int idx = blockIdx.x * blockDim.x + threadIdx.x;   // 0 .. 2*GROUPS_PER_T-1
    const bool isV = idx >= GROUPS_PER_T;
    int i = idx & (GROUPS_PER_T - 1);
    const float* src = isV ? V : K;
    uint16_t* dst = isV ? g_VH : g_KH;

    // i bits: e4 [0:4), h [4:8), s [8:19), n [19]
    int e4 = i & 15;
    int h  = (i >> 4) & 15;
    int s  = (i >> 8) & 2047;
    int n  = i >> 19;

    float4 v = *(const float4*)(src + ((((size_t)n * S_DIM + s) * H_DIM + h) << 6) + e4 * 4);
    uint2 o = make_uint2(pack_f16(v.x, v.y), pack_f16(v.z, v.w));
    *(uint2*)(dst + ((((size_t)n * H_DIM + h) * S_DIM + s) << 6) + e4 * 4) = o;
}

__global__ __launch_bounds__(128, 2) void attn_mma9_kernel(
    const float* __restrict__ Q,
    const float* __restrict__ M,
    float* __restrict__ O)
{
    __shared__ __align__(128) char smb[SMEM_BYTES];
    float* smf = (float*)smb;
    const uint32_t smu = (uint32_t)__cvta_generic_to_shared(smb);

    const int tid  = threadIdx.x;
    const int w    = tid >> 5;
    const int lane = tid & 31;
    const int g    = lane >> 2;
    const int tg   = lane & 3;
    const int mm   = lane >> 3;
    const int rr   = lane & 7;

    const int qt = blockIdx.x % (L_DIM / BR);
    const int nh = blockIdx.x / (L_DIM / BR);
    const int h  = nh % H_DIM;
    const int n  = nh / H_DIM;
    const int qbase = qt * BR;

    const float* Qg = Q + (((size_t)n * L_DIM + qbase) * H_DIM + h) * 64;

    // ---- Prologue: Q (128x64) -> smem scratch -> fp16 hi/mid A frags ----
    #pragma unroll
    for (int i = 0; i < 16; i++) {
        int idx = i * 128 + tid;
        int row = idx >> 4, c4 = idx & 15;
        float4 v = *(const float4*)(Qg + (size_t)row * (H_DIM * 64) + c4 * 4);
        *(float4*)(smf + row * QSTRIDE + c4 * 4) = v;
    }
    __syncthreads();

    uint32_t qh0[16], qm0[16], qh1[16], qm1[16];
    #pragma unroll
    for (int rg = 0; rg < 2; rg++) {
        uint32_t* qh = rg ? qh1 : qh0;
        uint32_t* qm = rg ? qm1 : qm0;
        const int r0 = w * 32 + rg * 16 + g;
        #pragma unroll
        for (int c = 0; c < 4; c++) {
            #pragma unroll
            for (int j = 0; j < 4; j++) {
                int row = r0 + ((j & 1) ? 8 : 0);
                int col = c * 16 + 2 * tg + ((j & 2) ? 8 : 0);
                float2 v = *(const float2*)(smf + row * QSTRIDE + col);
                float x0 = v.x * TEMP, x1 = v.y * TEMP;
                uint32_t hp = pack_f16(x0, x1);
                float2 hf = unpack_f16(hp);
                qh[c * 4 + j] = hp;
                qm[c * 4 + j] = pack_f16(x0 - hf.x, x1 - hf.y);
            }
        }
    }
    __syncthreads();   // scratch reads done before cp.async overwrites region

    float oacc0[32], oacc1[32];
    #pragma unroll
    for (int i = 0; i < 32; i++) { oacc0[i] = 0.0f; oacc1[i] = 0.0f; }
    float rs[4] = {0.0f, 0.0f, 0.0f, 0.0f};

    const uint32_t kadr0 = smu + OFF_KB + (uint32_t)(((mm >> 1) * 8 + rr) * KROWB + (mm & 1) * 16);
    const uint32_t vadr0 = smu + OFF_VB + (uint32_t)(((mm & 1) * 8 + rr) * VROWB + (mm >> 1) * 16);

    const float* Mr0 = M + (size_t)(qbase + w * 32 + g) * S_DIM + tg * 2;
    const float* Mr1 = Mr0 + (size_t)8 * S_DIM;
    const float* Mr2 = Mr0 + (size_t)16 * S_DIM;
    const float* Mr3 = Mr0 + (size_t)24 * S_DIM;

    // cp.async per-thread mapping: rows tid>>3 and +16, 16B chunk (tid&7)
    const int crow = tid >> 3;
    const int ccol = tid & 7;
    const uint16_t* KHb = g_KH + (((size_t)n * H_DIM + h) * S_DIM << 6) + ccol * 8;
    const uint16_t* VHb = g_VH + (((size_t)n * H_DIM + h) * S_DIM << 6) + ccol * 8;
    const uint32_t kdst_t = smu + OFF_KB + crow * KROWB + ccol * 16;
    const uint32_t vdst_t = smu + OFF_VB + crow * VROWB + ccol * 16;

    // issue tile 0
    {
        const uint16_t* ks = KHb;           // s0 = 0
        const uint16_t* vs = VHb;
        CP_ASYNC16(kdst_t,               ks + (size_t)crow * 64);
        CP_ASYNC16(kdst_t + 16 * KROWB,  ks + (size_t)(crow + 16) * 64);
        CP_ASYNC16(vdst_t,               vs + (size_t)crow * 64);
        CP_ASYNC16(vdst_t + 16 * VROWB,  vs + (size_t)(crow + 16) * 64);
        CP_COMMIT();
    }

    for (int t = 0; t < NTILES; ++t) {
        const int buf = t & 1;
        const int s0 = t * BC;

        CP_WAIT0();        // tile t data arrived
        __syncthreads();   // visible to all; everyone done reading buf^1 (tile t-1)

        // issue tile t+1 into the other buffer (hidden behind compute below)
        if (t + 1 < NTILES) {
            const uint32_t ko = (uint32_t)((1 - buf) * KBUFB);
            const uint32_t vo = (uint32_t)((1 - buf) * VBUFB);
            const uint16_t* ks = KHb + (size_t)(s0 + BC) * 64;
            const uint16_t* vs = VHb + (size_t)(s0 + BC) * 64;
            CP_ASYNC16(kdst_t + ko,              ks + (size_t)crow * 64);
            CP_ASYNC16(kdst_t + ko + 16 * KROWB, ks + (size_t)(crow + 16) * 64);
            CP_ASYNC16(vdst_t + vo,              vs + (size_t)crow * 64);
            CP_ASYNC16(vdst_t + vo + 16 * VROWB, vs + (size_t)(crow + 16) * 64);
            CP_COMMIT();
        }

        // ---- MMA1: S = (qh + qm) * kh, B frags via ldmatrix ----
        const uint32_t kadr = kadr0 + buf * KBUFB;
        float s0f[16], s1f[16];
        #pragma unroll
        for (int i = 0; i < 16; i++) { s0f[i] = 0.0f; s1f[i] = 0.0f; }
        #pragma unroll
        for (int c = 0; c < 4; c++) {
            uint32_t b00, b01, b10, b11, b20, b21, b30, b31;
            LDSM_X4(b00, b01, b10, b11, kadr + c * 32);          // nt 0,1
            LDSM_X4(b20, b21, b30, b31, kadr + c * 32 + 2304);   // nt 2,3
            mma_f16(s0f + 0,  qh0 + c * 4, b00, b01);
            mma_f16(s0f + 0,  qm0 + c * 4, b00, b01);
            mma_f16(s1f + 0,  qh1 + c * 4, b00, b01);
            mma_f16(s1f + 0,  qm1 + c * 4, b00, b01);
            mma_f16(s0f + 4,  qh0 + c * 4, b10, b11);
            mma_f16(s0f + 4,  qm0 + c * 4, b10, b11);
            mma_f16(s1f + 4,  qh1 + c * 4, b10, b11);
            mma_f16(s1f + 4,  qm1 + c * 4, b10, b11);
            mma_f16(s0f + 8,  qh0 + c * 4, b20, b21);
            mma_f16(s0f + 8,  qm0 + c * 4, b20, b21);
            mma_f16(s1f + 8,  qh1 + c * 4, b20, b21);
            mma_f16(s1f + 8,  qm1 + c * 4, b20, b21);
            mma_f16(s0f + 12, qh0 + c * 4, b30, b31);
            mma_f16(s0f + 12, qm0 + c * 4, b30, b31);
            mma_f16(s1f + 12, qh1 + c * 4, b30, b31);
            mma_f16(s1f + 12, qm1 + c * 4, b30, b31);
        }

        // ---- softmax -> P fp16x2 A-fragments in registers ----
        uint32_t u0[8], u1[8];
        #pragma unroll
        for (int nt = 0; nt < 4; nt++) {
            {
                float2 a = *(const float2*)(Mr0 + s0 + nt * 8);
                float2 b = *(const float2*)(Mr1 + s0 + nt * 8);
                float p0 = __expf(s0f[nt * 4 + 0] + TEMP * a.x);
                float p1 = __expf(s0f[nt * 4 + 1] + TEMP * a.y);
                float p2 = __expf(s0f[nt * 4 + 2] + TEMP * b.x);
                float p3 = __expf(s0f[nt * 4 + 3] + TEMP * b.y);
                uint32_t u01 = pack_f16(p0, p1);
                uint32_t u23 = pack_f16(p2, p3);
                float2 t01 = unpack_f16(u01);
                float2 t23 = unpack_f16(u23);
                rs[0] += t01.x + t01.y;
                rs[1] += t23.x + t23.y;
                u0[nt * 2 + 0] = u01;
                u0[nt * 2 + 1] = u23;
            }
            {
                float2 a = *(const float2*)(Mr2 + s0 + nt * 8);
                float2 b = *(const float2*)(Mr3 + s0 + nt * 8);
                float p0 = __expf(s1f[nt * 4 + 0] + TEMP * a.x);
                float p1 = __expf(s1f[nt * 4 + 1] + TEMP * a.y);
                float p2 = __expf(s1f[nt * 4 + 2] + TEMP * b.x);
                float p3 = __expf(s1f[nt * 4 + 3] + TEMP * b.y);
                uint32_t u01 = pack_f16(p0, p1);
                uint32_t u23 = pack_f16(p2, p3);
                float2 t01 = unpack_f16(u01);
                float2 t23 = unpack_f16(u23);
                rs[2] += t01.x + t01.y;
                rs[3] += t23.x + t23.y;
                u1[nt * 2 + 0] = u01;
                u1[nt * 2 + 1] = u23;
            }
        }

        // ---- MMA2: O += P * V; A from registers, B via ldmatrix.trans ----
        const uint32_t vadr = vadr0 + buf * VBUFB;
        #pragma unroll
        for (int kc = 0; kc < 2; kc++) {
            const uint32_t* a0 = u0 + 4 * kc;
            const uint32_t* a1 = u1 + 4 * kc;
            #pragma unroll
            for (int nvp = 0; nvp < 8; nvp += 2) {
                uint32_t v0, v1, v2, v3;
                LDSM_X4_T(v0, v1, v2, v3, vadr + kc * 2304 + nvp * 16);
                mma_f16(oacc0 + nvp * 4,     a0, v0, v1);
                mma_f16(oacc0 + nvp * 4 + 4, a0, v2, v3);
                mma_f16(oacc1 + nvp * 4,     a1, v0, v1);
                mma_f16(oacc1 + nvp * 4 + 4, a1, v2, v3);
            }
        }
    }

    // ---- epilogue ----
    #pragma unroll
    for (int i = 0; i < 4; i++) {
        rs[i] += __shfl_xor_sync(0xFFFFFFFFu, rs[i], 1);
        rs[i] += __shfl_xor_sync(0xFFFFFFFFu, rs[i], 2);
    }
    const int qrow0 = qbase + w * 32 + g;
    #pragma unroll
    for (int rg = 0; rg < 2; rg++) {
        const float* oacc = rg ? oacc1 : oacc0;
        const float inv0 = 1.0f / rs[rg * 2 + 0];
        const float inv1 = 1.0f / rs[rg * 2 + 1];
        float* Og0 = O + (((size_t)n * L_DIM + qrow0 + rg * 16) * H_DIM + h) * 64;
        float* Og1 = Og0 + (size_t)8 * H_DIM * 64;
        #pragma unroll
        for (int nt = 0; nt < 8; nt++) {
            int c = nt * 8 + tg * 2;
            float2 v0, v1;
            v0.x = oacc[nt * 4 + 0] * inv0;
            v0.y = oacc[nt * 4 + 1] * inv0;
            v1.x = oacc[nt * 4 + 2] * inv1;
            v1.y = oacc[nt * 4 + 3] * inv1;
            *(float2*)(Og0 + c) = v0;
            *(float2*)(Og1 + c) = v1;
        }
    }
}

extern "C" void kernel_launch(void* const* d_in, const int* in_sizes, int n_in,
                              void* d_out, int out_size)
{
    (void)in_sizes; (void)n_in; (void)out_size;
    const float* q = (const float*)d_in[0];
    const float* k = (const float*)d_in[1];
    const float* v = (const float*)d_in[2];
    const float* m = (const float*)d_in[3];
    float* o = (float*)d_out;

    cvt_kernel<<<(2 * GROUPS_PER_T) / 256, 256>>>(k, v);

    dim3 grid(N_DIM * H_DIM * (L_DIM / BR));   // 512
    dim3 block(128);
    attn_mma9_kernel<<<grid, block>>>(q, m, o);
}

// round 12
// speedup vs baseline: 1.0917x; 1.0917x over previous
#include <cuda_runtime.h>
#include <cuda_fp16.h>
#include <cstdint>
#include <cstddef>

// Flash attention, all-fp16 operand path, register-resident P, cp.async fp16
// tiles, m16-per-warp / 4 CTAs per SM (occupancy over per-warp reuse: the
// kernel is latency-bound at 8 warps/SM, L1 has headroom).
//   Prepass: K,V f32 (N,S,H,E) -> fp16 (N,H,S,E) __device__ scratch.
//   Main:    QK^T fp16 2-term split (m16n8k16); PV fp16 m16n8k16 f32-accum;
//            ldmatrix fragments; P in registers (C-frag == A-frag for k16).

#define N_DIM 2
#define L_DIM 2048
#define S_DIM 2048
#define H_DIM 16
#define BR 64
#define BC 32
#define NTILES (S_DIM / BC)
#define TEMP 0.125f

// smem byte layout
#define KROWB 144              // 64 fp16 = 128 B + 16 pad (ldmatrix conflict-free)
#define VROWB 144
#define KBUFB 4608             // 32 * 144
#define VBUFB 4608
#define OFF_KB 0               // 2 buffers -> 9216
#define OFF_VB 9216            // 2 buffers -> 9216 (end 18432)
#define QSTRIDE 68             // prologue scratch stride (floats); 64*68*4 = 17408
#define SMEM_BYTES 18432

// fp16 scratch, (N,H,S,E) layout
__device__ __align__(16) uint16_t g_KH[(size_t)N_DIM * H_DIM * S_DIM * 64];
__device__ __align__(16) uint16_t g_VH[(size_t)N_DIM * H_DIM * S_DIM * 64];

__device__ __forceinline__ uint32_t pack_f16(float lo, float hi) {
    uint32_t r; asm("cvt.rn.f16x2.f32 %0, %1, %2;" : "=r"(r) : "f"(hi), "f"(lo)); return r;
}
__device__ __forceinline__ float2 unpack_f16(uint32_t u) {
    __half2 h = *reinterpret_cast<__half2*>(&u);
    return __half22float2(h);
}

__device__ __forceinline__ void mma_f16(float* d, const uint32_t* a, uint32_t b0, uint32_t b1) {
    asm volatile(
        "mma.sync.aligned.m16n8k16.row.col.f32.f16.f16.f32 "
        "{%0,%1,%2,%3}, {%4,%5,%6,%7}, {%8,%9}, {%0,%1,%2,%3};"
        : "+f"(d[0]), "+f"(d[1]), "+f"(d[2]), "+f"(d[3])
        : "r"(a[0]), "r"(a[1]), "r"(a[2]), "r"(a[3]), "r"(b0), "r"(b1));
}

#define LDSM_X4(r0, r1, r2, r3, a) \
    asm volatile("ldmatrix.sync.aligned.m8n8.x4.shared.b16 {%0,%1,%2,%3}, [%4];" \
        : "=r"(r0), "=r"(r1), "=r"(r2), "=r"(r3) : "r"(a))
#define LDSM_X4_T(r0, r1, r2, r3, a) \
    asm volatile("ldmatrix.sync.aligned.m8n8.x4.trans.shared.b16 {%0,%1,%2,%3}, [%4];" \
        : "=r"(r0), "=r"(r1), "=r"(r2), "=r"(r3) : "r"(a))

#define CP_ASYNC16(dst, src) \
    asm volatile("cp.async.cg.shared.global [%0], [%1], 16;" :: "r"(dst), "l"(src))
#define CP_COMMIT() asm volatile("cp.async.commit_group;" ::: "memory")
#define CP_WAIT0()  asm volatile("cp.async.wait_group 0;" ::: "memory")

// ---- Prepass: f32 (N,S,H,E) -> fp16 (N,H,S,E) for K and V ----
#define GROUPS_PER_T ((N_DIM * S_DIM * H_DIM * 64) / 4)

__global__ __launch_bounds__(256) void cvt_kernel(
    const float* __restrict__ K, const float* __restrict__ V)
{
    int idx = blockIdx.x * blockDim.x + threadIdx.x;
    const bool isV = idx >= GROUPS_PER_T;
    int i = idx & (GROUPS_PER_T - 1);
    const float* src = isV ? V : K;
    uint16_t* dst = isV ? g_VH : g_KH;

    int e4 = i & 15;
    int h  = (i >> 4) & 15;
    int s  = (i >> 8) & 2047;
    int n  = i >> 19;

    float4 v = *(const float4*)(src + ((((size_t)n * S_DIM + s) * H_DIM + h) << 6) + e4 * 4);
    uint2 o = make_uint2(pack_f16(v.x, v.y), pack_f16(v.z, v.w));
    *(uint2*)(dst + ((((size_t)n * H_DIM + h) * S_DIM + s) << 6) + e4 * 4) = o;
}

__global__ __launch_bounds__(128, 4) void attn_mma10_kernel(
    const float* __restrict__ Q,
    const float* __restrict__ M,
    float* __restrict__ O)
{
    __shared__ __align__(128) char smb[SMEM_BYTES];
    float* smf = (float*)smb;
    const uint32_t smu = (uint32_t)__cvta_generic_to_shared(smb);

    const int tid  = threadIdx.x;
    const int w    = tid >> 5;
    const int lane = tid & 31;
    const int g    = lane >> 2;
    const int tg   = lane & 3;
    const int mm   = lane >> 3;
    const int rr   = lane & 7;

    const int qt = blockIdx.x % (L_DIM / BR);
    const int nh = blockIdx.x / (L_DIM / BR);
    const int h  = nh % H_DIM;
    const int n  = nh / H_DIM;
    const int qbase = qt * BR;

    const float* Qg = Q + (((size_t)n * L_DIM + qbase) * H_DIM + h) * 64;

    // ---- Prologue: Q (64x64) -> smem scratch -> fp16 hi/mid A frags ----
    #pragma unroll
    for (int i = 0; i < 8; i++) {
        int idx = i * 128 + tid;
        int row = idx >> 4, c4 = idx & 15;
        float4 v = *(const float4*)(Qg + (size_t)row * (H_DIM * 64) + c4 * 4);
        *(float4*)(smf + row * QSTRIDE + c4 * 4) = v;
    }
    __syncthreads();

    uint32_t qh[16], qm[16];
    {
        const int r0 = w * 16 + g;
        #pragma unroll
        for (int c = 0; c < 4; c++) {
            #pragma unroll
            for (int j = 0; j < 4; j++) {
                int row = r0 + ((j & 1) ? 8 : 0);
                int col = c * 16 + 2 * tg + ((j & 2) ? 8 : 0);
                float2 v = *(const float2*)(smf + row * QSTRIDE + col);
                float x0 = v.x * TEMP, x1 = v.y * TEMP;
                uint32_t hp = pack_f16(x0, x1);
                float2 hf = unpack_f16(hp);
                qh[c * 4 + j] = hp;
                qm[c * 4 + j] = pack_f16(x0 - hf.x, x1 - hf.y);
            }
        }
    }
    __syncthreads();   // scratch reads done before cp.async overwrites region

    float oacc[32];
    #pragma unroll
    for (int i = 0; i < 32; i++) oacc[i] = 0.0f;
    float rs0 = 0.0f, rs1 = 0.0f;

    const uint32_t kadr0 = smu + OFF_KB + (uint32_t)(((mm >> 1) * 8 + rr) * KROWB + (mm & 1) * 16);
    const uint32_t vadr0 = smu + OFF_VB + (uint32_t)(((mm & 1) * 8 + rr) * VROWB + (mm >> 1) * 16);

    const float* Mr0 = M + (size_t)(qbase + w * 16 + g) * S_DIM + tg * 2;
    const float* Mr1 = Mr0 + (size_t)8 * S_DIM;

    // cp.async per-thread mapping: rows tid>>3 and +16, 16B chunk (tid&7)
    const int crow = tid >> 3;
    const int ccol = tid & 7;
    const uint16_t* KHb = g_KH + (((size_t)n * H_DIM + h) * S_DIM << 6) + ccol * 8;
    const uint16_t* VHb = g_VH + (((size_t)n * H_DIM + h) * S_DIM << 6) + ccol * 8;
    const uint32_t kdst_t = smu + OFF_KB + crow * KROWB + ccol * 16;
    const uint32_t vdst_t = smu + OFF_VB + crow * VROWB + ccol * 16;

    // issue tile 0
    {
        CP_ASYNC16(kdst_t,               KHb + (size_t)crow * 64);
        CP_ASYNC16(kdst_t + 16 * KROWB,  KHb + (size_t)(crow + 16) * 64);
        CP_ASYNC16(vdst_t,               VHb + (size_t)crow * 64);
        CP_ASYNC16(vdst_t + 16 * VROWB,  VHb + (size_t)(crow + 16) * 64);
        CP_COMMIT();
    }

    for (int t = 0; t < NTILES; ++t) {
        const int buf = t & 1;
        const int s0 = t * BC;

        CP_WAIT0();        // tile t data arrived
        __syncthreads();   // visible; everyone done reading buf^1 (tile t-1)

        // issue tile t+1 into the other buffer (hidden behind compute below)
        if (t + 1 < NTILES) {
            const uint32_t ko = (uint32_t)((1 - buf) * KBUFB);
            const uint32_t vo = (uint32_t)((1 - buf) * VBUFB);
            const uint16_t* ks = KHb + (size_t)(s0 + BC) * 64;
            const uint16_t* vs = VHb + (size_t)(s0 + BC) * 64;
            CP_ASYNC16(kdst_t + ko,              ks + (size_t)crow * 64);
            CP_ASYNC16(kdst_t + ko + 16 * KROWB, ks + (size_t)(crow + 16) * 64);
            CP_ASYNC16(vdst_t + vo,              vs + (size_t)crow * 64);
            CP_ASYNC16(vdst_t + vo + 16 * VROWB, vs + (size_t)(crow + 16) * 64);
            CP_COMMIT();
        }

        // ---- MMA1: S = (qh + qm) * kh, B frags via ldmatrix ----
        const uint32_t kadr = kadr0 + buf * KBUFB;
        float sf[16];
        #pragma unroll
        for (int i = 0; i < 16; i++) sf[i] = 0.0f;
        #pragma unroll
        for (int c = 0; c < 4; c++) {
            uint32_t b00, b01, b10, b11, b20, b21, b30, b31;
            LDSM_X4(b00, b01, b10, b11, kadr + c * 32);          // nt 0,1
            LDSM_X4(b20, b21, b30, b31, kadr + c * 32 + 2304);   // nt 2,3
            mma_f16(sf + 0,  qh + c * 4, b00, b01);
            mma_f16(sf + 0,  qm + c * 4, b00, b01);
            mma_f16(sf + 4,  qh + c * 4, b10, b11);
            mma_f16(sf + 4,  qm + c * 4, b10, b11);
            mma_f16(sf + 8,  qh + c * 4, b20, b21);
            mma_f16(sf + 8,  qm + c * 4, b20, b21);
            mma_f16(sf + 12, qh + c * 4, b30, b31);
            mma_f16(sf + 12, qm + c * 4, b30, b31);
        }

        // ---- softmax -> P fp16x2 A-fragments in registers ----
        uint32_t u[8];
        #pragma unroll
        for (int nt = 0; nt < 4; nt++) {
            float2 a = *(const float2*)(Mr0 + s0 + nt * 8);
            float2 b = *(const float2*)(Mr1 + s0 + nt * 8);
            float p0 = __expf(sf[nt * 4 + 0] + TEMP * a.x);
            float p1 = __expf(sf[nt * 4 + 1] + TEMP * a.y);
            float p2 = __expf(sf[nt * 4 + 2] + TEMP * b.x);
            float p3 = __expf(sf[nt * 4 + 3] + TEMP * b.y);
            uint32_t u01 = pack_f16(p0, p1);
            uint32_t u23 = pack_f16(p2, p3);
            float2 t01 = unpack_f16(u01);
            float2 t23 = unpack_f16(u23);
            rs0 += t01.x + t01.y;
            rs1 += t23.x + t23.y;
            u[nt * 2 + 0] = u01;
            u[nt * 2 + 1] = u23;
        }

        // ---- MMA2: O += P * V; A from registers, B via ldmatrix.trans ----
        const uint32_t vadr = vadr0 + buf * VBUFB;
        #pragma unroll
        for (int kc = 0; kc < 2; kc++) {
            const uint32_t* a0 = u + 4 * kc;
            #pragma unroll
            for (int nvp = 0; nvp < 8; nvp += 2) {
                uint32_t v0, v1, v2, v3;
                LDSM_X4_T(v0, v1, v2, v3, vadr + kc * 2304 + nvp * 16);
                mma_f16(oacc + nvp * 4,     a0, v0, v1);
                mma_f16(oacc + nvp * 4 + 4, a0, v2, v3);
            }
        }
    }

    // ---- epilogue ----
    rs0 += __shfl_xor_sync(0xFFFFFFFFu, rs0, 1);
    rs0 += __shfl_xor_sync(0xFFFFFFFFu, rs0, 2);
    rs1 += __shfl_xor_sync(0xFFFFFFFFu, rs1, 1);
    rs1 += __shfl_xor_sync(0xFFFFFFFFu, rs1, 2);
    const float inv0 = 1.0f / rs0;
    const float inv1 = 1.0f / rs1;

    const int qrow0 = qbase + w * 16 + g;
    float* Og0 = O + (((size_t)n * L_DIM + qrow0) * H_DIM + h) * 64;
    float* Og1 = Og0 + (size_t)8 * H_DIM * 64;
    #pragma unroll
    for (int nt = 0; nt < 8; nt++) {
        int c = nt * 8 + tg * 2;
        float2 v0, v1;
        v0.x = oacc[nt * 4 + 0] * inv0;
        v0.y = oacc[nt * 4 + 1] * inv0;
        v1.x = oacc[nt * 4 + 2] * inv1;
        v1.y = oacc[nt * 4 + 3] * inv1;
        *(float2*)(Og0 + c) = v0;
        *(float2*)(Og1 + c) = v1;
    }
}

extern "C" void kernel_launch(void* const* d_in, const int* in_sizes, int n_in,
                              void* d_out, int out_size)
{
    (void)in_sizes; (void)n_in; (void)out_size;
    const float* q = (const float*)d_in[0];
    const float* k = (const float*)d_in[1];
    const float* v = (const float*)d_in[2];
    const float* m = (const float*)d_in[3];
    float* o = (float*)d_out;

    cvt_kernel<<<(2 * GROUPS_PER_T) / 256, 256>>>(k, v);

    dim3 grid(N_DIM * H_DIM * (L_DIM / BR));   // 1024
    dim3 block(128);
    attn_mma10_kernel<<<grid, block>>>(q, m, o);
}